// round 7
// baseline (speedup 1.0000x reference)
#include <cuda_runtime.h>
#include <cuda_bf16.h>
#include <cuda_fp16.h>
#include <cstdint>
#include <stdint.h>
#include <math.h>

#define NP 100000
#define NA 100000
#define DIN 256
#define DOUT 128
#define NE 1600000
#define SLOPE 0.2f
#define CAP 96

// ---------------- scratch (static device globals; allocation-free) ----------
__device__ __align__(16) float g_Wh_P[NP * DOUT];
__device__ __align__(16) float g_Wh_A[NA * DOUT];
__device__ __align__(16) __half g_m_p2p[NP * DOUT];
__device__ __align__(16) __half g_m_p2a[NP * DOUT];
__device__ __align__(16) __half g_m_a2p[NA * DOUT];
__device__ __align__(16) __half g_m_a2a[NA * DOUT];
__device__ float g_s_p2p_src[NP];
__device__ float g_s_p2p_dst[NP];
__device__ float g_s_p2a_src[NP];
__device__ float g_s_p2a_dst[NA];
__device__ float g_s_a2p_src[NA];
__device__ float g_s_a2p_dst[NP];
__device__ float g_s_a2a_src[NA];
__device__ float g_s_a2a_dst[NA];
__device__ __align__(16) int g_bkt[4][NP * CAP];
__device__ int g_cnt[4][NP];
// transposed/split weights: [6 matrices][128 N][256 K] bf16
__device__ __align__(16) __nv_bfloat16 g_Bhi[6 * 128 * 256];
__device__ __align__(16) __nv_bfloat16 g_Blo[6 * 128 * 256];

// ---------------- PTX helpers (baseline sm_103, NO 'a' features) ------------
__device__ __forceinline__ uint32_t smem_u32(const void* p) {
    uint32_t a;
    asm("{ .reg .u64 t; cvta.to.shared.u64 t, %1; cvt.u32.u64 %0, t; }"
        : "=r"(a) : "l"(p));
    return a;
}
__device__ __forceinline__ void ldsm_x4(uint32_t a[4], uint32_t addr) {
    asm volatile("ldmatrix.sync.aligned.m8n8.x4.shared.b16 {%0,%1,%2,%3}, [%4];"
                 : "=r"(a[0]), "=r"(a[1]), "=r"(a[2]), "=r"(a[3]) : "r"(addr));
}
__device__ __forceinline__ void ldsm_x2(uint32_t a[2], uint32_t addr) {
    asm volatile("ldmatrix.sync.aligned.m8n8.x2.shared.b16 {%0,%1}, [%2];"
                 : "=r"(a[0]), "=r"(a[1]) : "r"(addr));
}
__device__ __forceinline__ void mma_bf16(float c[4], const uint32_t a[4],
                                         const uint32_t b[2]) {
    asm volatile(
        "mma.sync.aligned.m16n8k16.row.col.f32.bf16.bf16.f32 "
        "{%0,%1,%2,%3}, {%4,%5,%6,%7}, {%8,%9}, {%0,%1,%2,%3};"
        : "+f"(c[0]), "+f"(c[1]), "+f"(c[2]), "+f"(c[3])
        : "r"(a[0]), "r"(a[1]), "r"(a[2]), "r"(a[3]), "r"(b[0]), "r"(b[1]));
}

// ---------------- weight prep: W[k][n] -> B[w][n][k] hi/lo bf16 -------------
__global__ void prep_w_kernel(const float* __restrict__ W0, const float* __restrict__ W1,
                              const float* __restrict__ W2, const float* __restrict__ W3,
                              const float* __restrict__ W4, const float* __restrict__ W5,
                              __nv_bfloat16* __restrict__ bhi,
                              __nv_bfloat16* __restrict__ blo)
{
    int i = blockIdx.x * blockDim.x + threadIdx.x;
    if (i >= 6 * 128 * 256) return;
    int w = i >> 15;
    int rem = i & 32767;
    int nrow = rem >> 8;
    int k = rem & 255;
    const float* W = (w == 0) ? W0 : (w == 1) ? W1 : (w == 2) ? W2
                   : (w == 3) ? W3 : (w == 4) ? W4 : W5;
    float v = W[k * 128 + nrow];
    __nv_bfloat16 h = __float2bfloat16(v);
    __nv_bfloat16 l = __float2bfloat16(v - __bfloat162float(h));
    bhi[i] = h;
    blo[i] = l;
}

// ---------------- HMMA GEMM with fused bias + s-dots + fp16 msg stores ------
#define ASTR 72
#define KCH 64
#define SM_AHI 0
#define SM_ALO 18432
#define SM_BHI 36864
#define SM_BLO 55296
#define GEMM_SMEM 73728

__device__ __forceinline__ void split1(float x, __nv_bfloat16& h, __nv_bfloat16& l) {
    h = __float2bfloat16(x);
    l = __float2bfloat16(x - __bfloat162float(h));
}

__global__ __launch_bounds__(256, 2)
void gemm_mma_kernel(const float* __restrict__ feat, int n,
                     const __nv_bfloat16* __restrict__ Bhi,
                     const __nv_bfloat16* __restrict__ Blo,
                     const float* __restrict__ b0, const float* __restrict__ b1,
                     const float* __restrict__ b2,
                     const float* __restrict__ aD1, const float* __restrict__ aD2,
                     const float* __restrict__ aS1, const float* __restrict__ aS2,
                     float* __restrict__ o0,
                     __half* __restrict__ o1h, __half* __restrict__ o2h,
                     float* __restrict__ sD1, float* __restrict__ sD2,
                     float* __restrict__ sS1, float* __restrict__ sS2)
{
    extern __shared__ __align__(16) char smem[];
    __shared__ float sacc[2][128];
    const uint32_t sbase = smem_u32(smem);

    const int w    = blockIdx.x;           // which weight matrix (0..2)
    const int row0 = blockIdx.y * 128;
    const int tid  = threadIdx.x;
    const int warp = tid >> 5;
    const int lane = tid & 31;

    const __nv_bfloat16* Bh = Bhi + (size_t)w * 128 * 256;
    const __nv_bfloat16* Bl = Blo + (size_t)w * 128 * 256;

    const int m_base = (warp >> 2) * 64;   // 0 or 64
    const int n_base = (warp & 3) * 32;    // 0,32,64,96

    float c[4][4][4];
#pragma unroll
    for (int mt = 0; mt < 4; mt++)
#pragma unroll
        for (int nt = 0; nt < 4; nt++)
#pragma unroll
            for (int r = 0; r < 4; r++) c[mt][nt][r] = 0.f;

    uint32_t aRow[4], bRow[4];
#pragma unroll
    for (int mt = 0; mt < 4; mt++) {
        int r = m_base + mt * 16 + (lane & 15);
        aRow[mt] = (uint32_t)(r * ASTR * 2) + (((uint32_t)lane >> 4) << 4);
    }
#pragma unroll
    for (int nt = 0; nt < 4; nt++) {
        int r = n_base + nt * 8 + (lane & 7);
        bRow[nt] = (uint32_t)(r * ASTR * 2) + ((((uint32_t)lane >> 3) & 1) << 4);
    }

    if (tid < 256) sacc[tid >> 7][tid & 127] = 0.f;

    for (int kc = 0; kc < DIN; kc += KCH) {
#pragma unroll
        for (int it = 0; it < 8; it++) {
            int idx = it * 256 + tid;        // 2048 float4s
            int r   = idx >> 4;
            int c4  = idx & 15;
            float4 v = make_float4(0.f, 0.f, 0.f, 0.f);
            if (row0 + r < n)
                v = *(const float4*)(feat + (size_t)(row0 + r) * DIN + kc + c4 * 4);
            __nv_bfloat16 h0, l0, h1, l1, h2, l2, h3, l3;
            split1(v.x, h0, l0); split1(v.y, h1, l1);
            split1(v.z, h2, l2); split1(v.w, h3, l3);
            __nv_bfloat162 hA = __halves2bfloat162(h0, h1);
            __nv_bfloat162 hB = __halves2bfloat162(h2, h3);
            __nv_bfloat162 lA = __halves2bfloat162(l0, l1);
            __nv_bfloat162 lB = __halves2bfloat162(l2, l3);
            uint32_t off = (uint32_t)((r * ASTR + c4 * 4) * 2);
            *(uint2*)(smem + SM_AHI + off) =
                make_uint2(*(uint32_t*)&hA, *(uint32_t*)&hB);
            *(uint2*)(smem + SM_ALO + off) =
                make_uint2(*(uint32_t*)&lA, *(uint32_t*)&lB);
        }
#pragma unroll
        for (int it = 0; it < 4; it++) {
            int idx = it * 256 + tid;        // 1024 int4s per precision
            int nr  = idx >> 3;
            int c16 = idx & 7;
            uint32_t off = (uint32_t)((nr * ASTR + c16 * 8) * 2);
            *(int4*)(smem + SM_BHI + off) =
                *(const int4*)(Bh + (size_t)nr * DIN + kc + c16 * 8);
            *(int4*)(smem + SM_BLO + off) =
                *(const int4*)(Bl + (size_t)nr * DIN + kc + c16 * 8);
        }
        __syncthreads();

#pragma unroll
        for (int ks = 0; ks < 4; ks++) {
            const uint32_t kofs = (uint32_t)(ks * 32);
            uint32_t bh[4][2], bl[4][2];
#pragma unroll
            for (int nt = 0; nt < 4; nt++) {
                ldsm_x2(bh[nt], sbase + SM_BHI + bRow[nt] + kofs);
                ldsm_x2(bl[nt], sbase + SM_BLO + bRow[nt] + kofs);
            }
#pragma unroll
            for (int mt = 0; mt < 4; mt++) {
                uint32_t ah[4], al[4];
                ldsm_x4(ah, sbase + SM_AHI + aRow[mt] + kofs);
                ldsm_x4(al, sbase + SM_ALO + aRow[mt] + kofs);
#pragma unroll
                for (int nt = 0; nt < 4; nt++) {
                    mma_bf16(c[mt][nt], ah, bh[nt]);   // hi*hi
                    mma_bf16(c[mt][nt], al, bh[nt]);   // lo*hi
                    mma_bf16(c[mt][nt], ah, bl[nt]);   // hi*lo
                }
            }
        }
        __syncthreads();
    }

    // ---- epilogue: bias + store (fp32 or fp16) + fused s-dots ----
    const float* bw = (w == 0) ? b0 : (w == 1) ? b1 : b2;
    const float* aq1 = (w == 0) ? aD1 : (w == 1) ? aS1 : aS2;
    const int lr = lane >> 2;
    const int lc = (lane & 3) * 2;
    float2 bv[4], a1v[4], a2v[4];
#pragma unroll
    for (int nt = 0; nt < 4; nt++) {
        int col = n_base + nt * 8 + lc;
        bv[nt]  = *(const float2*)(bw + col);
        a1v[nt] = *(const float2*)(aq1 + col);
        a2v[nt] = (w == 0) ? *(const float2*)(aD2 + col) : make_float2(0.f, 0.f);
    }

#pragma unroll
    for (int mt = 0; mt < 4; mt++) {
        int r1 = row0 + m_base + mt * 16 + lr;
        int r2 = r1 + 8;
        float pa1 = 0.f, pa2 = 0.f, pb1 = 0.f, pb2 = 0.f;
#pragma unroll
        for (int nt = 0; nt < 4; nt++) {
            int col = n_base + nt * 8 + lc;
            float v0 = c[mt][nt][0] + bv[nt].x;
            float v1 = c[mt][nt][1] + bv[nt].y;
            float v2 = c[mt][nt][2] + bv[nt].x;
            float v3 = c[mt][nt][3] + bv[nt].y;
            if (w == 0) {
                if (r1 < n) *(float2*)(o0 + (size_t)r1 * DOUT + col) = make_float2(v0, v1);
                if (r2 < n) *(float2*)(o0 + (size_t)r2 * DOUT + col) = make_float2(v2, v3);
            } else {
                __half* oh = (w == 1) ? o1h : o2h;
                if (r1 < n) *(__half2*)(oh + (size_t)r1 * DOUT + col) = __floats2half2_rn(v0, v1);
                if (r2 < n) *(__half2*)(oh + (size_t)r2 * DOUT + col) = __floats2half2_rn(v2, v3);
            }
            pa1 += v0 * a1v[nt].x + v1 * a1v[nt].y;
            pa2 += v2 * a1v[nt].x + v3 * a1v[nt].y;
            if (w == 0) {
                pb1 += v0 * a2v[nt].x + v1 * a2v[nt].y;
                pb2 += v2 * a2v[nt].x + v3 * a2v[nt].y;
            }
        }
        pa1 += __shfl_xor_sync(0xffffffffu, pa1, 1);
        pa1 += __shfl_xor_sync(0xffffffffu, pa1, 2);
        pa2 += __shfl_xor_sync(0xffffffffu, pa2, 1);
        pa2 += __shfl_xor_sync(0xffffffffu, pa2, 2);
        pb1 += __shfl_xor_sync(0xffffffffu, pb1, 1);
        pb1 += __shfl_xor_sync(0xffffffffu, pb1, 2);
        pb2 += __shfl_xor_sync(0xffffffffu, pb2, 1);
        pb2 += __shfl_xor_sync(0xffffffffu, pb2, 2);
        if ((lane & 3) == 0) {
            int lrow = m_base + mt * 16 + lr;
            atomicAdd(&sacc[0][lrow], pa1);
            atomicAdd(&sacc[0][lrow + 8], pa2);
            if (w == 0) {
                atomicAdd(&sacc[1][lrow], pb1);
                atomicAdd(&sacc[1][lrow + 8], pb2);
            }
        }
    }
    __syncthreads();
    if (tid < 128 && row0 + tid < n) {
        if (w == 0) {
            sD1[row0 + tid] = sacc[0][tid];
            sD2[row0 + tid] = sacc[1][tid];
        } else if (w == 1) {
            sS1[row0 + tid] = sacc[0][tid];
        } else {
            sS2[row0 + tid] = sacc[0][tid];
        }
    }
}

// ---------------- edge pipeline: zero, minimal scatter, fused gather --------
struct ScatParams {
    const int* src[4];
    const int* dst[4];
    int*       bkt[4];
    int*       cnt[4];
};

__global__ void zero_cnt_kernel(int* __restrict__ cnt)
{
    int i = blockIdx.x * blockDim.x + threadIdx.x;
    if (i < 4 * NP) cnt[i] = 0;
}

// Minimal scatter: just bucket the src index by dst. 1 atomic + 1 4B store.
__global__ void scatter4_kernel(ScatParams P)
{
    const int t = blockIdx.y;
    int i = blockIdx.x * blockDim.x + threadIdx.x;
    if (i >= NE) return;
    int s = P.src[t][i];
    int d = P.dst[t][i];
    int pos = atomicAdd(&P.cnt[t][d], 1);
    if (pos < CAP) P.bkt[t][(size_t)d * CAP + pos] = s;
}

// One edge type's softmax-weighted gather for one node (warp-collective).
// e recomputed here: e = leaky(ssrc[s] + sdst[node]).
__device__ __forceinline__ float4 gat_one(const int* __restrict__ cnt,
                                          const int* __restrict__ bkt,
                                          const __half* __restrict__ msg,
                                          const float* __restrict__ ssrc,
                                          float sd, int node, int lane)
{
    int c = cnt[node];
    if (c > CAP) c = CAP;
    float4 acc = make_float4(0.f, 0.f, 0.f, 0.f);
    if (c == 0) return acc;

    const int* bp = bkt + (size_t)node * CAP;
    int   sidx[3];
    float e[3];
#pragma unroll
    for (int k = 0; k < 3; k++) {
        int j = k * 32 + lane;
        if (j < c) {
            int s = bp[j];
            sidx[k] = s;
            float ev = __ldg(&ssrc[s]) + sd;
            e[k] = ev > 0.f ? ev : SLOPE * ev;
        } else {
            sidx[k] = 0;
            e[k] = -3.0e38f;
        }
    }
    float m = fmaxf(fmaxf(e[0], e[1]), e[2]);
#pragma unroll
    for (int o = 16; o > 0; o >>= 1)
        m = fmaxf(m, __shfl_xor_sync(0xffffffffu, m, o));

    float dsum = 0.f;
#pragma unroll
    for (int k = 0; k < 3; k++)
        if (k * 32 + lane < c) dsum += __expf(e[k] - m);
#pragma unroll
    for (int o = 16; o > 0; o >>= 1)
        dsum += __shfl_xor_sync(0xffffffffu, dsum, o);
    float inv = 1.f / dsum;

#pragma unroll
    for (int k = 0; k < 3; k++) {
        int lim = c - k * 32;
        if (lim <= 0) break;
        if (lim > 32) lim = 32;
        float ek = e[k];
        int   sk = sidx[k];
        for (int j = 0; j < lim; j++) {
            float w = __expf(__shfl_sync(0xffffffffu, ek, j) - m);
            int   s = __shfl_sync(0xffffffffu, sk, j);
            uint2 raw = *(const uint2*)(msg + (size_t)s * DOUT + lane * 4);
            float2 f01 = __half22float2(*(__half2*)&raw.x);
            float2 f23 = __half22float2(*(__half2*)&raw.y);
            acc.x += w * f01.x;
            acc.y += w * f01.y;
            acc.z += w * f23.x;
            acc.w += w * f23.y;
        }
    }
    acc.x *= inv; acc.y *= inv; acc.z *= inv; acc.w *= inv;
    return acc;
}

// Fused gather (2 edge types) + combine + ReLU -> writes final output.
__global__ void gather_combine_kernel(
    const int* __restrict__ cnt0, const int* __restrict__ bkt0,
    const __half* __restrict__ msg0, const float* __restrict__ ssrc0,
    const float* __restrict__ sdst0,
    const int* __restrict__ cnt1, const int* __restrict__ bkt1,
    const __half* __restrict__ msg1, const float* __restrict__ ssrc1,
    const float* __restrict__ sdst1,
    const float* __restrict__ Wh, float* __restrict__ out, int n)
{
    int node = (blockIdx.x * blockDim.x + threadIdx.x) >> 5;
    int lane = threadIdx.x & 31;
    if (node >= n) return;

    float sd0 = __ldg(&sdst0[node]);
    float sd1 = __ldg(&sdst1[node]);
    float4 r0 = gat_one(cnt0, bkt0, msg0, ssrc0, sd0, node, lane);
    float4 r1 = gat_one(cnt1, bkt1, msg1, ssrc1, sd1, node, lane);
    float4 v  = *(const float4*)(Wh + (size_t)node * DOUT + lane * 4);
    v.x = fmaxf(v.x + r0.x + r1.x, 0.f);
    v.y = fmaxf(v.y + r0.y + r1.y, 0.f);
    v.z = fmaxf(v.z + r0.z + r1.z, 0.f);
    v.w = fmaxf(v.w + r0.w + r1.w, 0.f);
    *(float4*)(out + (size_t)node * DOUT + lane * 4) = v;
}

// ---------------- launch ----------------------------------------------------
static void* sym_addr(const void* sym)
{
    void* p = nullptr;
    cudaGetSymbolAddress(&p, sym);
    return p;
}

extern "C" void kernel_launch(void* const* d_in, const int* in_sizes, int n_in,
                              void* d_out, int out_size)
{
    const float* feat_P  = (const float*)d_in[0];
    const float* feat_A  = (const float*)d_in[1];
    const int*   p2p_src = (const int*)d_in[2];
    const int*   p2p_dst = (const int*)d_in[3];
    const int*   p2a_src = (const int*)d_in[4];
    const int*   p2a_dst = (const int*)d_in[5];
    const int*   a2p_src = (const int*)d_in[6];
    const int*   a2p_dst = (const int*)d_in[7];
    const int*   a2a_src = (const int*)d_in[8];
    const int*   a2a_dst = (const int*)d_in[9];
    const float* W_P   = (const float*)d_in[10];
    const float* b_P   = (const float*)d_in[11];
    const float* W_A   = (const float*)d_in[12];
    const float* b_A   = (const float*)d_in[13];
    const float* W_p2p = (const float*)d_in[14];
    const float* b_p2p = (const float*)d_in[15];
    const float* W_p2a = (const float*)d_in[16];
    const float* b_p2a = (const float*)d_in[17];
    const float* W_a2p = (const float*)d_in[18];
    const float* b_a2p = (const float*)d_in[19];
    const float* W_a2a = (const float*)d_in[20];
    const float* b_a2a = (const float*)d_in[21];
    const float* a_p2p = (const float*)d_in[22];
    const float* a_p2a = (const float*)d_in[23];
    const float* a_a2p = (const float*)d_in[24];
    const float* a_a2a = (const float*)d_in[25];

    float* Wh_P  = (float*)sym_addr(g_Wh_P);
    float* Wh_A  = (float*)sym_addr(g_Wh_A);
    __half* m_p2p = (__half*)sym_addr(g_m_p2p);
    __half* m_p2a = (__half*)sym_addr(g_m_p2a);
    __half* m_a2p = (__half*)sym_addr(g_m_a2p);
    __half* m_a2a = (__half*)sym_addr(g_m_a2a);
    float* s_p2p_src = (float*)sym_addr(g_s_p2p_src);
    float* s_p2p_dst = (float*)sym_addr(g_s_p2p_dst);
    float* s_p2a_src = (float*)sym_addr(g_s_p2a_src);
    float* s_p2a_dst = (float*)sym_addr(g_s_p2a_dst);
    float* s_a2p_src = (float*)sym_addr(g_s_a2p_src);
    float* s_a2p_dst = (float*)sym_addr(g_s_a2p_dst);
    float* s_a2a_src = (float*)sym_addr(g_s_a2a_src);
    float* s_a2a_dst = (float*)sym_addr(g_s_a2a_dst);
    int* bkt = (int*)sym_addr(g_bkt);
    int* cnt = (int*)sym_addr(g_cnt);
    __nv_bfloat16* Bhi = (__nv_bfloat16*)sym_addr(g_Bhi);
    __nv_bfloat16* Blo = (__nv_bfloat16*)sym_addr(g_Blo);

    float* out = (float*)d_out;

    // 0) weight transpose + bf16 split
    prep_w_kernel<<<(6 * 128 * 256 + 255) / 256, 256>>>(
        W_P, W_p2p, W_p2a, W_A, W_a2p, W_a2a, Bhi, Blo);
    // zero counters early (independent of GEMM)
    zero_cnt_kernel<<<(4 * NP + 255) / 256, 256>>>(cnt);

    // 1) HMMA GEMMs with fused bias + s-dots; msg outputs fp16
    cudaFuncSetAttribute(gemm_mma_kernel,
                         cudaFuncAttributeMaxDynamicSharedMemorySize, GEMM_SMEM);
    {
        dim3 gridP(3, (NP + 127) / 128);
        gemm_mma_kernel<<<gridP, 256, GEMM_SMEM>>>(
            feat_P, NP, Bhi, Blo, b_P, b_p2p, b_p2a,
            a_p2p + DOUT, a_a2p + DOUT, a_p2p, a_p2a,
            Wh_P, m_p2p, m_p2a,
            s_p2p_dst, s_a2p_dst, s_p2p_src, s_p2a_src);
        dim3 gridA(3, (NA + 127) / 128);
        gemm_mma_kernel<<<gridA, 256, GEMM_SMEM>>>(
            feat_A, NA, Bhi + 3 * 128 * 256, Blo + 3 * 128 * 256,
            b_A, b_a2p, b_a2a,
            a_p2a + DOUT, a_a2a + DOUT, a_a2p, a_a2a,
            Wh_A, m_a2p, m_a2a,
            s_p2a_dst, s_a2a_dst, s_a2p_src, s_a2a_src);
    }

    // 2) minimal scatter (4 types in one launch; independent of GEMM results)
    ScatParams SP;
    SP.src[0] = p2p_src; SP.dst[0] = p2p_dst;
    SP.src[1] = a2p_src; SP.dst[1] = a2p_dst;
    SP.src[2] = p2a_src; SP.dst[2] = p2a_dst;
    SP.src[3] = a2a_src; SP.dst[3] = a2a_dst;
    for (int t = 0; t < 4; t++) {
        SP.bkt[t] = bkt + (size_t)t * NP * CAP;
        SP.cnt[t] = cnt + (size_t)t * NP;
    }
    {
        dim3 gs((NE + 255) / 256, 4);
        scatter4_kernel<<<gs, 256>>>(SP);
    }

    // 3) fused gather + combine + ReLU -> final output
    {
        int grid = (NP * 32 + 255) / 256;
        gather_combine_kernel<<<grid, 256>>>(
            SP.cnt[0], SP.bkt[0], m_p2p, s_p2p_src, s_p2p_dst,
            SP.cnt[1], SP.bkt[1], m_a2p, s_a2p_src, s_a2p_dst,
            Wh_P, out, NP);
        gather_combine_kernel<<<grid, 256>>>(
            SP.cnt[2], SP.bkt[2], m_p2a, s_p2a_src, s_p2a_dst,
            SP.cnt[3], SP.bkt[3], m_a2a, s_a2a_src, s_a2a_dst,
            Wh_A, out + (size_t)NP * DOUT, NA);
    }
}

// round 8
// speedup vs baseline: 1.2764x; 1.2764x over previous
#include <cuda_runtime.h>
#include <cuda_bf16.h>
#include <cuda_fp16.h>
#include <cstdint>
#include <stdint.h>
#include <math.h>

#define NP 100000
#define NA 100000
#define DIN 256
#define DOUT 128
#define NE 1600000
#define SLOPE 0.2f
#define CAP 96

// ---------------- scratch (static device globals; allocation-free) ----------
__device__ __align__(16) float g_Wh_P[NP * DOUT];
__device__ __align__(16) float g_Wh_A[NA * DOUT];
__device__ __align__(16) __half g_m_p2p[NP * DOUT];
__device__ __align__(16) __half g_m_p2a[NP * DOUT];
__device__ __align__(16) __half g_m_a2p[NA * DOUT];
__device__ __align__(16) __half g_m_a2a[NA * DOUT];
__device__ float g_s_p2p_src[NP];
__device__ float g_s_p2p_dst[NP];
__device__ float g_s_p2a_src[NP];
__device__ float g_s_p2a_dst[NA];
__device__ float g_s_a2p_src[NA];
__device__ float g_s_a2p_dst[NP];
__device__ float g_s_a2a_src[NA];
__device__ float g_s_a2a_dst[NA];
__device__ __align__(16) int2 g_bkt[4][NP * CAP];
__device__ int g_cnt[4][NP];
// transposed/split weights: [6 matrices][128 N][256 K] bf16
__device__ __align__(16) __nv_bfloat16 g_Bhi[6 * 128 * 256];
__device__ __align__(16) __nv_bfloat16 g_Blo[6 * 128 * 256];

// ---------------- PTX helpers (baseline sm_103, NO 'a' features) ------------
__device__ __forceinline__ uint32_t smem_u32(const void* p) {
    uint32_t a;
    asm("{ .reg .u64 t; cvta.to.shared.u64 t, %1; cvt.u32.u64 %0, t; }"
        : "=r"(a) : "l"(p));
    return a;
}
__device__ __forceinline__ void ldsm_x4(uint32_t a[4], uint32_t addr) {
    asm volatile("ldmatrix.sync.aligned.m8n8.x4.shared.b16 {%0,%1,%2,%3}, [%4];"
                 : "=r"(a[0]), "=r"(a[1]), "=r"(a[2]), "=r"(a[3]) : "r"(addr));
}
__device__ __forceinline__ void mma_bf16(float c[4], const uint32_t a[4],
                                         const uint32_t b[2]) {
    asm volatile(
        "mma.sync.aligned.m16n8k16.row.col.f32.bf16.bf16.f32 "
        "{%0,%1,%2,%3}, {%4,%5,%6,%7}, {%8,%9}, {%0,%1,%2,%3};"
        : "+f"(c[0]), "+f"(c[1]), "+f"(c[2]), "+f"(c[3])
        : "r"(a[0]), "r"(a[1]), "r"(a[2]), "r"(a[3]), "r"(b[0]), "r"(b[1]));
}

// ---------------- weight prep: W[k][n] -> B[w][n][k] hi/lo bf16 -------------
__global__ void prep_w_kernel(const float* __restrict__ W0, const float* __restrict__ W1,
                              const float* __restrict__ W2, const float* __restrict__ W3,
                              const float* __restrict__ W4, const float* __restrict__ W5,
                              __nv_bfloat16* __restrict__ bhi,
                              __nv_bfloat16* __restrict__ blo)
{
    int i = blockIdx.x * blockDim.x + threadIdx.x;
    if (i >= 6 * 128 * 256) return;
    int w = i >> 15;
    int rem = i & 32767;
    int nrow = rem >> 8;
    int k = rem & 255;
    const float* W = (w == 0) ? W0 : (w == 1) ? W1 : (w == 2) ? W2
                   : (w == 3) ? W3 : (w == 4) ? W4 : W5;
    float v = W[k * 128 + nrow];
    __nv_bfloat16 h = __float2bfloat16(v);
    __nv_bfloat16 l = __float2bfloat16(v - __bfloat162float(h));
    bhi[i] = h;
    blo[i] = l;
}

// ---------------- HMMA GEMM with fused bias + s-dots + fp16 msg stores ------
#define ASTR 72
#define KCH 64
#define SM_AHI 0
#define SM_ALO 18432
#define SM_BHI 36864
#define SM_BLO 55296
#define GEMM_SMEM 73728

__device__ __forceinline__ void split1(float x, __nv_bfloat16& h, __nv_bfloat16& l) {
    h = __float2bfloat16(x);
    l = __float2bfloat16(x - __bfloat162float(h));
}

__global__ __launch_bounds__(256, 2)
void gemm_mma_kernel(const float* __restrict__ feat, int n,
                     const __nv_bfloat16* __restrict__ Bhi,
                     const __nv_bfloat16* __restrict__ Blo,
                     const float* __restrict__ b0, const float* __restrict__ b1,
                     const float* __restrict__ b2,
                     const float* __restrict__ aD1, const float* __restrict__ aD2,
                     const float* __restrict__ aS1, const float* __restrict__ aS2,
                     float* __restrict__ o0,
                     __half* __restrict__ o1h, __half* __restrict__ o2h,
                     float* __restrict__ sD1, float* __restrict__ sD2,
                     float* __restrict__ sS1, float* __restrict__ sS2)
{
    extern __shared__ __align__(16) char smem[];
    __shared__ float sacc[2][128];
    const uint32_t sbase = smem_u32(smem);

    const int w    = blockIdx.x;           // which weight matrix (0..2)
    const int row0 = blockIdx.y * 128;
    const int tid  = threadIdx.x;
    const int warp = tid >> 5;
    const int lane = tid & 31;

    const __nv_bfloat16* Bh = Bhi + (size_t)w * 128 * 256;
    const __nv_bfloat16* Bl = Blo + (size_t)w * 128 * 256;

    const int m_base = (warp >> 2) * 64;   // 0 or 64
    const int n_base = (warp & 3) * 32;    // 0,32,64,96

    float c[4][4][4];
#pragma unroll
    for (int mt = 0; mt < 4; mt++)
#pragma unroll
        for (int nt = 0; nt < 4; nt++)
#pragma unroll
            for (int r = 0; r < 4; r++) c[mt][nt][r] = 0.f;

    uint32_t aRow[4], bRow4[2];
#pragma unroll
    for (int mt = 0; mt < 4; mt++) {
        int r = m_base + mt * 16 + (lane & 15);
        aRow[mt] = (uint32_t)(r * ASTR * 2) + (((uint32_t)lane >> 4) << 4);
    }
    // B via ldsm_x4: lanes 0-15 -> rows [n0..n0+8) k-halves, lanes 16-31 -> rows +8
#pragma unroll
    for (int np = 0; np < 2; np++) {
        int r = n_base + np * 16 + (((int)lane >> 4) << 3) + (lane & 7);
        bRow4[np] = (uint32_t)(r * ASTR * 2) + ((((uint32_t)lane >> 3) & 1) << 4);
    }

    if (tid < 256) sacc[tid >> 7][tid & 127] = 0.f;

    for (int kc = 0; kc < DIN; kc += KCH) {
#pragma unroll
        for (int it = 0; it < 8; it++) {
            int idx = it * 256 + tid;        // 2048 float4s
            int r   = idx >> 4;
            int c4  = idx & 15;
            float4 v = make_float4(0.f, 0.f, 0.f, 0.f);
            if (row0 + r < n)
                v = *(const float4*)(feat + (size_t)(row0 + r) * DIN + kc + c4 * 4);
            __nv_bfloat16 h0, l0, h1, l1, h2, l2, h3, l3;
            split1(v.x, h0, l0); split1(v.y, h1, l1);
            split1(v.z, h2, l2); split1(v.w, h3, l3);
            __nv_bfloat162 hA = __halves2bfloat162(h0, h1);
            __nv_bfloat162 hB = __halves2bfloat162(h2, h3);
            __nv_bfloat162 lA = __halves2bfloat162(l0, l1);
            __nv_bfloat162 lB = __halves2bfloat162(l2, l3);
            uint32_t off = (uint32_t)((r * ASTR + c4 * 4) * 2);
            *(uint2*)(smem + SM_AHI + off) =
                make_uint2(*(uint32_t*)&hA, *(uint32_t*)&hB);
            *(uint2*)(smem + SM_ALO + off) =
                make_uint2(*(uint32_t*)&lA, *(uint32_t*)&lB);
        }
#pragma unroll
        for (int it = 0; it < 4; it++) {
            int idx = it * 256 + tid;        // 1024 int4s per precision
            int nr  = idx >> 3;
            int c16 = idx & 7;
            uint32_t off = (uint32_t)((nr * ASTR + c16 * 8) * 2);
            *(int4*)(smem + SM_BHI + off) =
                *(const int4*)(Bh + (size_t)nr * DIN + kc + c16 * 8);
            *(int4*)(smem + SM_BLO + off) =
                *(const int4*)(Bl + (size_t)nr * DIN + kc + c16 * 8);
        }
        __syncthreads();

#pragma unroll
        for (int ks = 0; ks < 4; ks++) {
            const uint32_t kofs = (uint32_t)(ks * 32);
            uint32_t bh[4][2], bl[4][2];
#pragma unroll
            for (int np = 0; np < 2; np++) {
                uint32_t t4[4];
                ldsm_x4(t4, sbase + SM_BHI + bRow4[np] + kofs);
                bh[2 * np][0] = t4[0]; bh[2 * np][1] = t4[1];
                bh[2 * np + 1][0] = t4[2]; bh[2 * np + 1][1] = t4[3];
                ldsm_x4(t4, sbase + SM_BLO + bRow4[np] + kofs);
                bl[2 * np][0] = t4[0]; bl[2 * np][1] = t4[1];
                bl[2 * np + 1][0] = t4[2]; bl[2 * np + 1][1] = t4[3];
            }
#pragma unroll
            for (int mt = 0; mt < 4; mt++) {
                uint32_t ah[4], al[4];
                ldsm_x4(ah, sbase + SM_AHI + aRow[mt] + kofs);
                ldsm_x4(al, sbase + SM_ALO + aRow[mt] + kofs);
#pragma unroll
                for (int nt = 0; nt < 4; nt++) {
                    mma_bf16(c[mt][nt], ah, bh[nt]);   // hi*hi
                    mma_bf16(c[mt][nt], al, bh[nt]);   // lo*hi
                    mma_bf16(c[mt][nt], ah, bl[nt]);   // hi*lo
                }
            }
        }
        __syncthreads();
    }

    // ---- epilogue: bias + store (fp32 or fp16) + fused s-dots ----
    const float* bw = (w == 0) ? b0 : (w == 1) ? b1 : b2;
    const float* aq1 = (w == 0) ? aD1 : (w == 1) ? aS1 : aS2;
    const int lr = lane >> 2;
    const int lc = (lane & 3) * 2;
    float2 bv[4], a1v[4], a2v[4];
#pragma unroll
    for (int nt = 0; nt < 4; nt++) {
        int col = n_base + nt * 8 + lc;
        bv[nt]  = *(const float2*)(bw + col);
        a1v[nt] = *(const float2*)(aq1 + col);
        a2v[nt] = (w == 0) ? *(const float2*)(aD2 + col) : make_float2(0.f, 0.f);
    }

#pragma unroll
    for (int mt = 0; mt < 4; mt++) {
        int r1 = row0 + m_base + mt * 16 + lr;
        int r2 = r1 + 8;
        float pa1 = 0.f, pa2 = 0.f, pb1 = 0.f, pb2 = 0.f;
#pragma unroll
        for (int nt = 0; nt < 4; nt++) {
            int col = n_base + nt * 8 + lc;
            float v0 = c[mt][nt][0] + bv[nt].x;
            float v1 = c[mt][nt][1] + bv[nt].y;
            float v2 = c[mt][nt][2] + bv[nt].x;
            float v3 = c[mt][nt][3] + bv[nt].y;
            if (w == 0) {
                if (r1 < n) *(float2*)(o0 + (size_t)r1 * DOUT + col) = make_float2(v0, v1);
                if (r2 < n) *(float2*)(o0 + (size_t)r2 * DOUT + col) = make_float2(v2, v3);
            } else {
                __half* oh = (w == 1) ? o1h : o2h;
                if (r1 < n) *(__half2*)(oh + (size_t)r1 * DOUT + col) = __floats2half2_rn(v0, v1);
                if (r2 < n) *(__half2*)(oh + (size_t)r2 * DOUT + col) = __floats2half2_rn(v2, v3);
            }
            pa1 += v0 * a1v[nt].x + v1 * a1v[nt].y;
            pa2 += v2 * a1v[nt].x + v3 * a1v[nt].y;
            if (w == 0) {
                pb1 += v0 * a2v[nt].x + v1 * a2v[nt].y;
                pb2 += v2 * a2v[nt].x + v3 * a2v[nt].y;
            }
        }
        pa1 += __shfl_xor_sync(0xffffffffu, pa1, 1);
        pa1 += __shfl_xor_sync(0xffffffffu, pa1, 2);
        pa2 += __shfl_xor_sync(0xffffffffu, pa2, 1);
        pa2 += __shfl_xor_sync(0xffffffffu, pa2, 2);
        pb1 += __shfl_xor_sync(0xffffffffu, pb1, 1);
        pb1 += __shfl_xor_sync(0xffffffffu, pb1, 2);
        pb2 += __shfl_xor_sync(0xffffffffu, pb2, 1);
        pb2 += __shfl_xor_sync(0xffffffffu, pb2, 2);
        if ((lane & 3) == 0) {
            int lrow = m_base + mt * 16 + lr;
            atomicAdd(&sacc[0][lrow], pa1);
            atomicAdd(&sacc[0][lrow + 8], pa2);
            if (w == 0) {
                atomicAdd(&sacc[1][lrow], pb1);
                atomicAdd(&sacc[1][lrow + 8], pb2);
            }
        }
    }
    __syncthreads();
    if (tid < 128 && row0 + tid < n) {
        if (w == 0) {
            sD1[row0 + tid] = sacc[0][tid];
            sD2[row0 + tid] = sacc[1][tid];
        } else if (w == 1) {
            sS1[row0 + tid] = sacc[0][tid];
        } else {
            sS2[row0 + tid] = sacc[0][tid];
        }
    }
}

// ---------------- edge pipeline ---------------------------------------------
struct EdgeParams {
    const int*   src[4];
    const int*   dst[4];
    const float* ssrc[4];
    const float* sdst[4];
    int2*        bkt[4];
    int*         cnt[4];
};

__global__ void zero_cnt_kernel(int* __restrict__ cnt)
{
    int i = blockIdx.x * blockDim.x + threadIdx.x;
    if (i < 4 * NP) cnt[i] = 0;
}

// Scatter with e precompute: 2 random 4B loads, 1 atomic, 1 8B store.
__global__ void scatter4_kernel(EdgeParams P)
{
    const int t = blockIdx.y;
    int i = blockIdx.x * blockDim.x + threadIdx.x;
    if (i >= NE) return;
    int s = P.src[t][i];
    int d = P.dst[t][i];
    float e = __ldg(&P.ssrc[t][s]) + __ldg(&P.sdst[t][d]);
    e = e > 0.f ? e : SLOPE * e;
    int pos = atomicAdd(&P.cnt[t][d], 1);
    if (pos < CAP) P.bkt[t][(size_t)d * CAP + pos] = make_int2(s, __float_as_int(e));
}

// One type's softmax-weighted gather for one node (warp-collective, R6 loop).
__device__ __forceinline__ float4 gat_one(const int* __restrict__ cnt,
                                          const int2* __restrict__ bkt,
                                          const __half* __restrict__ msg,
                                          int node, int lane)
{
    int c = cnt[node];
    if (c > CAP) c = CAP;
    float4 acc = make_float4(0.f, 0.f, 0.f, 0.f);
    if (c == 0) return acc;
    const int2* bp = bkt + (size_t)node * CAP;

    float m = -3.0e38f;
    for (int j = lane; j < c; j += 32) m = fmaxf(m, __int_as_float(bp[j].y));
#pragma unroll
    for (int o = 16; o > 0; o >>= 1)
        m = fmaxf(m, __shfl_xor_sync(0xffffffffu, m, o));

    float dsum = 0.f;
    for (int j = lane; j < c; j += 32) dsum += __expf(__int_as_float(bp[j].y) - m);
#pragma unroll
    for (int o = 16; o > 0; o >>= 1)
        dsum += __shfl_xor_sync(0xffffffffu, dsum, o);
    float inv = 1.f / dsum;

    for (int j = 0; j < c; j++) {
        int2 b = bp[j];                     // broadcast load
        float w = __expf(__int_as_float(b.y) - m);
        uint2 raw = *(const uint2*)(msg + (size_t)b.x * DOUT + lane * 4);
        float2 f01 = __half22float2(*(__half2*)&raw.x);
        float2 f23 = __half22float2(*(__half2*)&raw.y);
        acc.x += w * f01.x;
        acc.y += w * f01.y;
        acc.z += w * f23.x;
        acc.w += w * f23.y;
    }
    acc.x *= inv; acc.y *= inv; acc.z *= inv; acc.w *= inv;
    return acc;
}

// Fused: gather both incoming edge types + combine + ReLU -> final output.
__global__ void gather_combine_kernel(
    const int* __restrict__ cnt0, const int2* __restrict__ bkt0,
    const __half* __restrict__ msg0,
    const int* __restrict__ cnt1, const int2* __restrict__ bkt1,
    const __half* __restrict__ msg1,
    const float* __restrict__ Wh, float* __restrict__ out, int n)
{
    int node = (blockIdx.x * blockDim.x + threadIdx.x) >> 5;
    int lane = threadIdx.x & 31;
    if (node >= n) return;

    float4 r0 = gat_one(cnt0, bkt0, msg0, node, lane);
    float4 r1 = gat_one(cnt1, bkt1, msg1, node, lane);
    float4 v  = *(const float4*)(Wh + (size_t)node * DOUT + lane * 4);
    v.x = fmaxf(v.x + r0.x + r1.x, 0.f);
    v.y = fmaxf(v.y + r0.y + r1.y, 0.f);
    v.z = fmaxf(v.z + r0.z + r1.z, 0.f);
    v.w = fmaxf(v.w + r0.w + r1.w, 0.f);
    *(float4*)(out + (size_t)node * DOUT + lane * 4) = v;
}

// ---------------- launch ----------------------------------------------------
static void* sym_addr(const void* sym)
{
    void* p = nullptr;
    cudaGetSymbolAddress(&p, sym);
    return p;
}

extern "C" void kernel_launch(void* const* d_in, const int* in_sizes, int n_in,
                              void* d_out, int out_size)
{
    const float* feat_P  = (const float*)d_in[0];
    const float* feat_A  = (const float*)d_in[1];
    const int*   p2p_src = (const int*)d_in[2];
    const int*   p2p_dst = (const int*)d_in[3];
    const int*   p2a_src = (const int*)d_in[4];
    const int*   p2a_dst = (const int*)d_in[5];
    const int*   a2p_src = (const int*)d_in[6];
    const int*   a2p_dst = (const int*)d_in[7];
    const int*   a2a_src = (const int*)d_in[8];
    const int*   a2a_dst = (const int*)d_in[9];
    const float* W_P   = (const float*)d_in[10];
    const float* b_P   = (const float*)d_in[11];
    const float* W_A   = (const float*)d_in[12];
    const float* b_A   = (const float*)d_in[13];
    const float* W_p2p = (const float*)d_in[14];
    const float* b_p2p = (const float*)d_in[15];
    const float* W_p2a = (const float*)d_in[16];
    const float* b_p2a = (const float*)d_in[17];
    const float* W_a2p = (const float*)d_in[18];
    const float* b_a2p = (const float*)d_in[19];
    const float* W_a2a = (const float*)d_in[20];
    const float* b_a2a = (const float*)d_in[21];
    const float* a_p2p = (const float*)d_in[22];
    const float* a_p2a = (const float*)d_in[23];
    const float* a_a2p = (const float*)d_in[24];
    const float* a_a2a = (const float*)d_in[25];

    float* Wh_P  = (float*)sym_addr(g_Wh_P);
    float* Wh_A  = (float*)sym_addr(g_Wh_A);
    __half* m_p2p = (__half*)sym_addr(g_m_p2p);
    __half* m_p2a = (__half*)sym_addr(g_m_p2a);
    __half* m_a2p = (__half*)sym_addr(g_m_a2p);
    __half* m_a2a = (__half*)sym_addr(g_m_a2a);
    float* s_p2p_src = (float*)sym_addr(g_s_p2p_src);
    float* s_p2p_dst = (float*)sym_addr(g_s_p2p_dst);
    float* s_p2a_src = (float*)sym_addr(g_s_p2a_src);
    float* s_p2a_dst = (float*)sym_addr(g_s_p2a_dst);
    float* s_a2p_src = (float*)sym_addr(g_s_a2p_src);
    float* s_a2p_dst = (float*)sym_addr(g_s_a2p_dst);
    float* s_a2a_src = (float*)sym_addr(g_s_a2a_src);
    float* s_a2a_dst = (float*)sym_addr(g_s_a2a_dst);
    int2* bkt = (int2*)sym_addr(g_bkt);
    int*  cnt = (int*)sym_addr(g_cnt);
    __nv_bfloat16* Bhi = (__nv_bfloat16*)sym_addr(g_Bhi);
    __nv_bfloat16* Blo = (__nv_bfloat16*)sym_addr(g_Blo);

    float* out = (float*)d_out;

    // 0) weight transpose + bf16 split; zero counters
    prep_w_kernel<<<(6 * 128 * 256 + 255) / 256, 256>>>(
        W_P, W_p2p, W_p2a, W_A, W_a2p, W_a2a, Bhi, Blo);
    zero_cnt_kernel<<<(4 * NP + 255) / 256, 256>>>(cnt);

    // 1) HMMA GEMMs with fused bias + s-dots; msg outputs fp16
    cudaFuncSetAttribute(gemm_mma_kernel,
                         cudaFuncAttributeMaxDynamicSharedMemorySize, GEMM_SMEM);
    {
        dim3 gridP(3, (NP + 127) / 128);
        gemm_mma_kernel<<<gridP, 256, GEMM_SMEM>>>(
            feat_P, NP, Bhi, Blo, b_P, b_p2p, b_p2a,
            a_p2p + DOUT, a_a2p + DOUT, a_p2p, a_p2a,
            Wh_P, m_p2p, m_p2a,
            s_p2p_dst, s_a2p_dst, s_p2p_src, s_p2a_src);
        dim3 gridA(3, (NA + 127) / 128);
        gemm_mma_kernel<<<gridA, 256, GEMM_SMEM>>>(
            feat_A, NA, Bhi + 3 * 128 * 256, Blo + 3 * 128 * 256,
            b_A, b_a2p, b_a2a,
            a_p2a + DOUT, a_a2a + DOUT, a_a2p, a_a2a,
            Wh_A, m_a2p, m_a2a,
            s_p2a_dst, s_a2a_dst, s_a2p_src, s_a2a_src);
    }

    // 2) scatter with e precompute (4 types in one launch)
    EdgeParams EP;
    EP.src[0] = p2p_src; EP.dst[0] = p2p_dst; EP.ssrc[0] = s_p2p_src; EP.sdst[0] = s_p2p_dst;
    EP.src[1] = a2p_src; EP.dst[1] = a2p_dst; EP.ssrc[1] = s_a2p_src; EP.sdst[1] = s_a2p_dst;
    EP.src[2] = p2a_src; EP.dst[2] = p2a_dst; EP.ssrc[2] = s_p2a_src; EP.sdst[2] = s_p2a_dst;
    EP.src[3] = a2a_src; EP.dst[3] = a2a_dst; EP.ssrc[3] = s_a2a_src; EP.sdst[3] = s_a2a_dst;
    for (int t = 0; t < 4; t++) {
        EP.bkt[t] = bkt + (size_t)t * NP * CAP;
        EP.cnt[t] = cnt + (size_t)t * NP;
    }
    {
        dim3 gs((NE + 255) / 256, 4);
        scatter4_kernel<<<gs, 256>>>(EP);
    }

    // 3) fused gather + combine + ReLU -> final output
    {
        int grid = (NP * 32 + 255) / 256;
        gather_combine_kernel<<<grid, 256>>>(
            EP.cnt[0], EP.bkt[0], m_p2p,
            EP.cnt[1], EP.bkt[1], m_a2p,
            Wh_P, out, NP);
        gather_combine_kernel<<<grid, 256>>>(
            EP.cnt[2], EP.bkt[2], m_p2a,
            EP.cnt[3], EP.bkt[3], m_a2a,
            Wh_A, out + (size_t)NP * DOUT, NA);
    }
}